// round 10
// baseline (speedup 1.0000x reference)
#include <cuda_runtime.h>
#include <cuda_bf16.h>
#include <cstdint>
#include <math.h>

#define LL   8
#define NN   16384
#define KC   16
#define DD   256
#define D4   (4*DD)
#define D3   (3*DD)
#define NTOT (LL*NN)            // 131072

#define SW64(o) ((o) ^ (((o) >> 3) & 0x30))
#define TILE32 8192             // one 128x32 bf16 tile (64B rows, SW64)
#define STG 32768u              // gemm_mma stage: Ahi|Alo|Bhi|Blo x 8KB
#define STGF 24576u             // fused stage: Ahi 4K|Alo 4K|Bhi 8K|Blo 8K

__device__ __forceinline__ uint32_t smem_u32(const void* p) {
    uint32_t a;
    asm("{ .reg .u64 t; cvta.to.shared.u64 t, %1; cvt.u32.u64 %0, t; }" : "=r"(a) : "l"(p));
    return a;
}
__device__ __forceinline__ void ldsm_x4(uint32_t& r0, uint32_t& r1, uint32_t& r2,
                                        uint32_t& r3, uint32_t addr) {
    asm volatile("ldmatrix.sync.aligned.m8n8.x4.shared.b16 {%0,%1,%2,%3}, [%4];"
                 : "=r"(r0), "=r"(r1), "=r"(r2), "=r"(r3) : "r"(addr));
}
__device__ __forceinline__ void mma16816(float* c, const uint32_t* a, const uint32_t* b) {
    asm volatile("mma.sync.aligned.m16n8k16.row.col.f32.bf16.bf16.f32 "
                 "{%0,%1,%2,%3}, {%4,%5,%6,%7}, {%8,%9}, {%0,%1,%2,%3};"
                 : "+f"(c[0]), "+f"(c[1]), "+f"(c[2]), "+f"(c[3])
                 : "r"(a[0]), "r"(a[1]), "r"(a[2]), "r"(a[3]), "r"(b[0]), "r"(b[1]));
}
__device__ __forceinline__ float sigmoid_fast(float z) {
    float t;
    asm("tanh.approx.f32 %0, %1;" : "=f"(t) : "f"(0.5f * z));
    return fmaf(0.5f, t, 0.5f);
}
__device__ __forceinline__ float sigmoid_acc(float z) {
    return 1.f / (1.f + expf(-z));
}
#define CP_ASYNC16(dst, src) \
    asm volatile("cp.async.cg.shared.global [%0], [%1], 16;" :: "r"(dst), "l"(src))
#define CP_COMMIT asm volatile("cp.async.commit_group;" ::: "memory")
#define CP_WAIT2  asm volatile("cp.async.wait_group 2;" ::: "memory")
#define CP_WAIT1  asm volatile("cp.async.wait_group 1;" ::: "memory")
#define CP_WAIT0  asm volatile("cp.async.wait_group 0;" ::: "memory")

// ---------------- scratch (device globals) ---------------------------------
__device__ float g_Wf  [NTOT * DD];
__device__ float g_Hu  [NN * DD];
__device__ float g_f   [NN * DD];
// A operands: 128x32 bf16 tiles, 8 per 128-row block (K=256)
__device__ __align__(1024) unsigned char g_Axhi[NTOT/128 * 8 * TILE32];
__device__ __align__(1024) unsigned char g_Axlo[NTOT/128 * 8 * TILE32];
__device__ __align__(1024) unsigned char g_Ahshi[NN/128 * 8 * TILE32];
__device__ __align__(1024) unsigned char g_Ahslo[NN/128 * 8 * TILE32];
__device__ __align__(1024) unsigned char g_Ahhi [NN/128 * 8 * TILE32];
__device__ __align__(1024) unsigned char g_Ahlo [NN/128 * 8 * TILE32];
// B tiles: Wf: 0..15 (2nb x 8kc) | U_f: 16..31 | B_ext: 32..127 ((gate*2+nb) x 16kc)
__device__ __align__(1024) unsigned char g_Bhi[128 * TILE32];
__device__ __align__(1024) unsigned char g_Blo[128 * TILE32];

// ---------------- weight prep ----------------------------------------------
__device__ __forceinline__ void put_b(unsigned tile, int n_loc, int k_loc, float v) {
    __nv_bfloat16 hi = __float2bfloat16(v);
    __nv_bfloat16 lo = __float2bfloat16(v - __bfloat162float(hi));
    unsigned off = tile * TILE32 + SW64((unsigned)(n_loc * 64 + k_loc * 2));
    *(__nv_bfloat16*)(g_Bhi + off) = hi;
    *(__nv_bfloat16*)(g_Blo + off) = lo;
}
__global__ __launch_bounds__(256)
void prep_small(const float* __restrict__ W_w, const float* __restrict__ U_f)
{
    int idx = blockIdx.x * blockDim.x + threadIdx.x;
    int n = idx & 255, k = idx >> 8;
    put_b( 0 + (n >> 7) * 8 + (k >> 5), n & 127, k & 31, W_w[k * 1024 + n]);
    put_b(16 + (n >> 7) * 8 + (k >> 5), n & 127, k & 31, U_f[k * 256 + n]);
}
// B_ext regrouped per gate: gate g = n/256, dim = n%256, nb = dim>>7
// tile = 32 + (g*2 + nb)*16 + kc
__global__ __launch_bounds__(256)
void prep_ext(const float* __restrict__ W_w, const float* __restrict__ U_iuo)
{
    int idx = blockIdx.x * blockDim.x + threadIdx.x;
    if (idx >= 512 * 768) return;
    int n = idx % 768, k = idx / 768;
    float v = (k < 256) ? U_iuo[k * 768 + n] : W_w[(k - 256) * 1024 + 256 + n];
    int g = n / 256, dim = n % 256;
    put_b(32 + (g * 2 + (dim >> 7)) * 16 + (k >> 5), dim & 127, k & 31, v);
}

// ---------------- x -> bf16 hi/lo tiles -------------------------------------
__global__ __launch_bounds__(256)
void xconv_kernel(const float* __restrict__ x)
{
    int t = blockIdx.x * blockDim.x + threadIdx.x;
    int n = t >> 6, c4 = t & 63;
    float4 v = *(const float4*)&x[(size_t)t * 4];
    __nv_bfloat162 h0, h1, l0, l1;
    h0.x = __float2bfloat16(v.x); h0.y = __float2bfloat16(v.y);
    h1.x = __float2bfloat16(v.z); h1.y = __float2bfloat16(v.w);
    l0.x = __float2bfloat16(v.x - __bfloat162float(h0.x));
    l0.y = __float2bfloat16(v.y - __bfloat162float(h0.y));
    l1.x = __float2bfloat16(v.z - __bfloat162float(h1.x));
    l1.y = __float2bfloat16(v.w - __bfloat162float(h1.y));
    size_t tile = (size_t)(n >> 7) * 8 + (c4 >> 3);
    unsigned off = SW64((unsigned)((n & 127) * 64 + (c4 & 7) * 8));
    uint2 hh, ll;
    hh.x = *(uint32_t*)&h0; hh.y = *(uint32_t*)&h1;
    ll.x = *(uint32_t*)&l0; ll.y = *(uint32_t*)&l1;
    *(uint2*)(g_Axhi + tile * TILE32 + off) = hh;
    *(uint2*)(g_Axlo + tile * TILE32 + off) = ll;
}

// ---------------- 256-thread HMMA GEMM, 128x128 tile, 3-stage (Wf/Hu) ------
__global__ __launch_bounds__(256, 2)
void gemm_mma(const unsigned char* __restrict__ A0h, const unsigned char* __restrict__ A0l,
              const unsigned char* __restrict__ A1h, const unsigned char* __restrict__ A1l,
              int kchunks, int btile_base,
              const float* __restrict__ bias, float* __restrict__ C, int Nc)
{
    extern __shared__ char smem[];
    const uint32_t sb = smem_u32(smem);
    const int tid = threadIdx.x, wid = tid >> 5, lane = tid & 31;
    const int wm = wid & 3, wn = wid >> 2;
    const int mb = blockIdx.y, bn = blockIdx.x * 128;

    float acc[2][8][4];
#pragma unroll
    for (int i = 0; i < 2; i++)
#pragma unroll
        for (int j = 0; j < 8; j++)
#pragma unroll
            for (int q = 0; q < 4; q++) acc[i][j][q] = 0.f;

    const int a_row16 = (lane & 7) + ((lane >> 3) & 1) * 8;
    const int a_kb    = (lane >> 4) * 16;
    const int b_row16 = (lane & 7) + ((lane >> 4) << 3);
    const int b_kb    = ((lane >> 3) & 1) * 16;

    uint32_t aRow[2], aXor[2], bRow[4], bXor[4];
#pragma unroll
    for (int mt = 0; mt < 2; mt++) {
        uint32_t r = (uint32_t)(wm * 32 + mt * 16 + a_row16);
        aRow[mt] = r * 64u; aXor[mt] = (r & 6) * 8u;
    }
#pragma unroll
    for (int np = 0; np < 4; np++) {
        uint32_t r = (uint32_t)(wn * 64 + np * 16 + b_row16);
        bRow[np] = 16384u + r * 64u; bXor[np] = (r & 6) * 8u;
    }

    auto load_stage = [&](int stg, int kc) {
        const unsigned char *ah, *al;
        int kcl;
        if (kc < 8) { ah = A0h; al = A0l; kcl = kc; }
        else        { ah = A1h; al = A1l; kcl = kc - 8; }
        size_t at = ((size_t)mb * 8 + kcl) * TILE32;
        size_t bt = (size_t)(btile_base + blockIdx.x * kchunks + kc) * TILE32;
        const unsigned char* srcs[4] = { ah + at, al + at, g_Bhi + bt, g_Blo + bt };
        uint32_t base = sb + (uint32_t)stg * STG;
#pragma unroll
        for (int j = 0; j < 4; j++) {
            uint32_t d = base + j * TILE32 + tid * 16;
            const unsigned char* s = srcs[j] + tid * 16;
            CP_ASYNC16(d, s);
            CP_ASYNC16(d + 4096, s + 4096);
        }
        CP_COMMIT;
    };

    load_stage(0, 0);
    load_stage(1, 1);
    load_stage(2, 2);

    int stg_i = 0;
    for (int kc = 0; kc < kchunks; kc++) {
        if      (kc + 2 < kchunks) CP_WAIT2;
        else if (kc + 1 < kchunks) CP_WAIT1;
        else                       CP_WAIT0;
        __syncthreads();

        const uint32_t stg = sb + (uint32_t)stg_i * STG;
#pragma unroll
        for (int ks = 0; ks < 2; ks++) {
            const uint32_t ka = (uint32_t)(ks * 32 + a_kb);
            const uint32_t kb = (uint32_t)(ks * 32 + b_kb);
            uint32_t av[2][4], bv[4][4];
#pragma unroll
            for (int mt = 0; mt < 2; mt++)
                ldsm_x4(av[mt][0], av[mt][1], av[mt][2], av[mt][3],
                        stg + aRow[mt] + (ka ^ aXor[mt]));
#pragma unroll
            for (int np = 0; np < 4; np++)
                ldsm_x4(bv[np][0], bv[np][1], bv[np][2], bv[np][3],
                        stg + bRow[np] + (kb ^ bXor[np]));
#pragma unroll
            for (int mt = 0; mt < 2; mt++)
#pragma unroll
                for (int nt = 0; nt < 8; nt++)
                    mma16816(acc[mt][nt], av[mt], &bv[nt >> 1][(nt & 1) * 2]);
#pragma unroll
            for (int mt = 0; mt < 2; mt++)
                ldsm_x4(av[mt][0], av[mt][1], av[mt][2], av[mt][3],
                        stg + TILE32 + aRow[mt] + (ka ^ aXor[mt]));
#pragma unroll
            for (int mt = 0; mt < 2; mt++)
#pragma unroll
                for (int nt = 0; nt < 8; nt++)
                    mma16816(acc[mt][nt], av[mt], &bv[nt >> 1][(nt & 1) * 2]);
#pragma unroll
            for (int mt = 0; mt < 2; mt++)
                ldsm_x4(av[mt][0], av[mt][1], av[mt][2], av[mt][3],
                        stg + aRow[mt] + (ka ^ aXor[mt]));
#pragma unroll
            for (int np = 0; np < 4; np++)
                ldsm_x4(bv[np][0], bv[np][1], bv[np][2], bv[np][3],
                        stg + TILE32 + bRow[np] + (kb ^ bXor[np]));
#pragma unroll
            for (int mt = 0; mt < 2; mt++)
#pragma unroll
                for (int nt = 0; nt < 8; nt++)
                    mma16816(acc[mt][nt], av[mt], &bv[nt >> 1][(nt & 1) * 2]);
        }
        __syncthreads();
        if (kc + 3 < kchunks) load_stage(stg_i, kc + 3);
        stg_i = (stg_i == 2) ? 0 : stg_i + 1;
    }

    const int r0 = lane >> 2, c0 = (lane & 3) * 2;
    const int bm = mb * 128;
#pragma unroll
    for (int mt = 0; mt < 2; mt++) {
#pragma unroll
        for (int nt = 0; nt < 8; nt++) {
            int row = bm + wm * 32 + mt * 16 + r0;
            int col = bn + wn * 64 + nt * 8 + c0;
            float b0 = 0.f, b1 = 0.f;
            if (bias) { b0 = bias[col]; b1 = bias[col + 1]; }
            float2 v0, v1;
            v0.x = acc[mt][nt][0] + b0; v0.y = acc[mt][nt][1] + b1;
            v1.x = acc[mt][nt][2] + b0; v1.y = acc[mt][nt][3] + b1;
            *(float2*)&C[(size_t)row * Nc + col]       = v0;
            *(float2*)&C[(size_t)(row + 8) * Nc + col] = v1;
        }
    }
}

// ---------------- fused iuo GEMM + gates: CTA 64(M) x 128(dims) ------------
// Three sequential gate K-loops (u, i, o); tanh(u)/c held in registers.
// Writes out_h/out_c f32 + h bf16 hi/lo tiles. No iuo global buffer.
__global__ __launch_bounds__(256, 2)
void gemm_iuo_gates(const unsigned char* __restrict__ Ahsh, const unsigned char* __restrict__ Ahsl,
                    const unsigned char* __restrict__ Axh,  const unsigned char* __restrict__ Axl,
                    const float* __restrict__ Wb,       // = W_b + 256 (i,u,o biases)
                    const float* __restrict__ fbuf,
                    float* __restrict__ out_h, float* __restrict__ out_c)
{
    extern __shared__ char smem[];   // 3 stages x [Ahi 4K|Alo 4K|Bhi 8K|Blo 8K]
    const uint32_t sb = smem_u32(smem);
    const int tid = threadIdx.x, wid = tid >> 5, lane = tid & 31;
    const int wm = wid & 1, wn = wid >> 1;       // wm: 2x32 rows, wn: 4x32 dims
    const int bx = blockIdx.x;                   // dim block (0..1)
    const int my = blockIdx.y;                   // 64-row block (0..255)
    const int rb = my >> 1;                      // 128-row tile block
    const unsigned half = (unsigned)(my & 1) * 4096u;

    const int a_row16 = (lane & 7) + ((lane >> 3) & 1) * 8;
    const int a_kb    = (lane >> 4) * 16;
    const int b_row16 = (lane & 7) + ((lane >> 4) << 3);
    const int b_kb    = ((lane >> 3) & 1) * 16;

    uint32_t aRow[2], aXor[2], bRow[2], bXor[2];
#pragma unroll
    for (int mt = 0; mt < 2; mt++) {
        uint32_t r = (uint32_t)(wm * 32 + mt * 16 + a_row16);   // 0..63
        aRow[mt] = r * 64u; aXor[mt] = (r & 6) * 8u;
    }
#pragma unroll
    for (int np = 0; np < 2; np++) {
        uint32_t r = (uint32_t)(wn * 32 + np * 16 + b_row16);   // 0..127
        bRow[np] = 8192u + r * 64u; bXor[np] = (r & 6) * 8u;    // Bhi at 8K, Blo at 16K
    }

    auto load_stage = [&](int stg, int kc, int g) {
        const unsigned char *ah, *al;
        int kcl;
        if (kc < 8) { ah = Ahsh; al = Ahsl; kcl = kc; }
        else        { ah = Axh;  al = Axl;  kcl = kc - 8; }
        size_t at = ((size_t)rb * 8 + kcl) * TILE32 + half;
        size_t bt = (size_t)(32 + (g * 2 + bx) * 16 + kc) * TILE32;
        uint32_t base = sb + (uint32_t)stg * STGF;
        CP_ASYNC16(base + tid * 16,          ah + at + tid * 16);
        CP_ASYNC16(base + 4096 + tid * 16,   al + at + tid * 16);
        CP_ASYNC16(base + 8192 + tid * 16,   g_Bhi + bt + tid * 16);
        CP_ASYNC16(base + 12288 + tid * 16,  g_Bhi + bt + 4096 + tid * 16);
        CP_ASYNC16(base + 16384 + tid * 16,  g_Blo + bt + tid * 16);
        CP_ASYNC16(base + 20480 + tid * 16,  g_Blo + bt + 4096 + tid * 16);
        CP_COMMIT;
    };

    float held[2][4][4];
    const int r0 = lane >> 2, c0 = (lane & 3) * 2;
    const int gate_order[3] = {1, 0, 2};   // u, i, o

#pragma unroll 1
    for (int gi = 0; gi < 3; gi++) {
        const int g = gate_order[gi];

        float acc[2][4][4];
#pragma unroll
        for (int i = 0; i < 2; i++)
#pragma unroll
            for (int j = 0; j < 4; j++)
#pragma unroll
                for (int q = 0; q < 4; q++) acc[i][j][q] = 0.f;

        load_stage(0, 0, g);
        load_stage(1, 1, g);
        load_stage(2, 2, g);

        int stg_i = 0;
        for (int kc = 0; kc < 16; kc++) {
            if      (kc + 2 < 16) CP_WAIT2;
            else if (kc + 1 < 16) CP_WAIT1;
            else                  CP_WAIT0;
            __syncthreads();

            const uint32_t stg = sb + (uint32_t)stg_i * STGF;
#pragma unroll
            for (int ks = 0; ks < 2; ks++) {
                const uint32_t ka = (uint32_t)(ks * 32 + a_kb);
                const uint32_t kb = (uint32_t)(ks * 32 + b_kb);
                uint32_t av[2][4], bv[2][4];
                // pass 1: A-hi x B-hi
#pragma unroll
                for (int mt = 0; mt < 2; mt++)
                    ldsm_x4(av[mt][0], av[mt][1], av[mt][2], av[mt][3],
                            stg + aRow[mt] + (ka ^ aXor[mt]));
#pragma unroll
                for (int np = 0; np < 2; np++)
                    ldsm_x4(bv[np][0], bv[np][1], bv[np][2], bv[np][3],
                            stg + bRow[np] + (kb ^ bXor[np]));
#pragma unroll
                for (int mt = 0; mt < 2; mt++)
#pragma unroll
                    for (int nt = 0; nt < 4; nt++)
                        mma16816(acc[mt][nt], av[mt], &bv[nt >> 1][(nt & 1) * 2]);
                // pass 2: A-lo x B-hi (reuse B frags)
#pragma unroll
                for (int mt = 0; mt < 2; mt++)
                    ldsm_x4(av[mt][0], av[mt][1], av[mt][2], av[mt][3],
                            stg + 4096u + aRow[mt] + (ka ^ aXor[mt]));
#pragma unroll
                for (int mt = 0; mt < 2; mt++)
#pragma unroll
                    for (int nt = 0; nt < 4; nt++)
                        mma16816(acc[mt][nt], av[mt], &bv[nt >> 1][(nt & 1) * 2]);
                // pass 3: A-hi x B-lo
#pragma unroll
                for (int mt = 0; mt < 2; mt++)
                    ldsm_x4(av[mt][0], av[mt][1], av[mt][2], av[mt][3],
                            stg + aRow[mt] + (ka ^ aXor[mt]));
#pragma unroll
                for (int np = 0; np < 2; np++)
                    ldsm_x4(bv[np][0], bv[np][1], bv[np][2], bv[np][3],
                            stg + 8192u + bRow[np] + (kb ^ bXor[np]));
#pragma unroll
                for (int mt = 0; mt < 2; mt++)
#pragma unroll
                    for (int nt = 0; nt < 4; nt++)
                        mma16816(acc[mt][nt], av[mt], &bv[nt >> 1][(nt & 1) * 2]);
            }
            __syncthreads();
            if (kc + 3 < 16) load_stage(stg_i, kc + 3, g);
            stg_i = (stg_i == 2) ? 0 : stg_i + 1;
        }

        // ---- per-gate epilogue (thread-local; accurate math) ----
#pragma unroll
        for (int mt = 0; mt < 2; mt++) {
#pragma unroll
            for (int nt = 0; nt < 4; nt++) {
                const int row = my * 64 + wm * 32 + mt * 16 + r0;
                const int d   = bx * 128 + wn * 32 + nt * 8 + c0;
                const float b0 = Wb[g * 256 + d], b1 = Wb[g * 256 + d + 1];
                if (g == 1) {                       // u: hold tanh(u)
                    held[mt][nt][0] = tanhf(acc[mt][nt][0] + b0);
                    held[mt][nt][1] = tanhf(acc[mt][nt][1] + b1);
                    held[mt][nt][2] = tanhf(acc[mt][nt][2] + b0);
                    held[mt][nt][3] = tanhf(acc[mt][nt][3] + b1);
                } else if (g == 0) {                // i: c = sig(i)*tanh(u)+f
                    float2 f0 = *(const float2*)&fbuf[(size_t)row * DD + d];
                    float2 f1 = *(const float2*)&fbuf[(size_t)(row + 8) * DD + d];
                    float cc0 = sigmoid_acc(acc[mt][nt][0] + b0) * held[mt][nt][0] + f0.x;
                    float cc1 = sigmoid_acc(acc[mt][nt][1] + b1) * held[mt][nt][1] + f0.y;
                    float cc2 = sigmoid_acc(acc[mt][nt][2] + b0) * held[mt][nt][2] + f1.x;
                    float cc3 = sigmoid_acc(acc[mt][nt][3] + b1) * held[mt][nt][3] + f1.y;
                    *(float2*)&out_c[(size_t)row * DD + d]       = make_float2(cc0, cc1);
                    *(float2*)&out_c[(size_t)(row + 8) * DD + d] = make_float2(cc2, cc3);
                    held[mt][nt][0] = cc0; held[mt][nt][1] = cc1;
                    held[mt][nt][2] = cc2; held[mt][nt][3] = cc3;
                } else {                            // o: h = sig(o)*tanh(c)
                    float h0 = sigmoid_acc(acc[mt][nt][0] + b0) * tanhf(held[mt][nt][0]);
                    float h1 = sigmoid_acc(acc[mt][nt][1] + b1) * tanhf(held[mt][nt][1]);
                    float h2 = sigmoid_acc(acc[mt][nt][2] + b0) * tanhf(held[mt][nt][2]);
                    float h3 = sigmoid_acc(acc[mt][nt][3] + b1) * tanhf(held[mt][nt][3]);
                    *(float2*)&out_h[(size_t)row * DD + d]       = make_float2(h0, h1);
                    *(float2*)&out_h[(size_t)(row + 8) * DD + d] = make_float2(h2, h3);
                    // h -> bf16 hi/lo tiles
#pragma unroll
                    for (int rr = 0; rr < 2; rr++) {
                        float v0 = rr ? h2 : h0, v1 = rr ? h3 : h1;
                        int r = row + rr * 8;
                        __nv_bfloat162 hb, lb;
                        hb.x = __float2bfloat16(v0); hb.y = __float2bfloat16(v1);
                        lb.x = __float2bfloat16(v0 - __bfloat162float(hb.x));
                        lb.y = __float2bfloat16(v1 - __bfloat162float(hb.y));
                        size_t tile = (size_t)(r >> 7) * 8 + (d >> 5);
                        unsigned off = SW64((unsigned)((r & 127) * 64 + (d & 31) * 2));
                        *(uint32_t*)(g_Ahhi + tile * TILE32 + off) = *(uint32_t*)&hb;
                        *(uint32_t*)(g_Ahlo + tile * TILE32 + off) = *(uint32_t*)&lb;
                    }
                }
            }
        }
    }
}

// ---------------- gather: 8 nodes/block, 8 dims/thread, f32 tables ---------
__global__ __launch_bounds__(256)
void gather_kernel(const int* __restrict__ idx,
                   const float* __restrict__ h_prev,
                   const float* __restrict__ c_prev,
                   const float* __restrict__ Hu,
                   const float* __restrict__ Wf,
                   float* __restrict__ f)
{
    const int nb = blockIdx.x * 8;
    const int t  = threadIdx.x;
    const int ln = t >> 5;
    const int n  = nb + ln;
    const int d8 = (t & 31) * 8;

    __shared__ int sidx[8][KC];
    if (t < 128) sidx[t >> 4][t & 15] = idx[(nb + (t >> 4)) * KC + (t & 15)];
    __syncthreads();

    float hs[8] = {0,0,0,0,0,0,0,0};
    float fs[8] = {0,0,0,0,0,0,0,0};
    if (h_prev) {
        float4 wf0 = *(const float4*)&Wf[(size_t)n * DD + d8];
        float4 wf1 = *(const float4*)&Wf[(size_t)n * DD + d8 + 4];
        const float wf[8] = {wf0.x, wf0.y, wf0.z, wf0.w, wf1.x, wf1.y, wf1.z, wf1.w};
#pragma unroll
        for (int k = 0; k < KC; k++) {
            int j = sidx[ln][k];
            if (j >= 1) {
                size_t r = (size_t)(j - 1) * DD + d8;
                float4 h0 = *(const float4*)&h_prev[r];
                float4 h1 = *(const float4*)&h_prev[r + 4];
                float4 u0 = *(const float4*)&Hu[r];
                float4 u1 = *(const float4*)&Hu[r + 4];
                float4 c0 = *(const float4*)&c_prev[r];
                float4 c1 = *(const float4*)&c_prev[r + 4];
                const float hv[8] = {h0.x, h0.y, h0.z, h0.w, h1.x, h1.y, h1.z, h1.w};
                const float uv[8] = {u0.x, u0.y, u0.z, u0.w, u1.x, u1.y, u1.z, u1.w};
                const float cv[8] = {c0.x, c0.y, c0.z, c0.w, c1.x, c1.y, c1.z, c1.w};
#pragma unroll
                for (int q = 0; q < 8; q++) {
                    hs[q] += hv[q];
                    fs[q] += sigmoid_fast(wf[q] + uv[q]) * cv[q];
                }
            }
        }
    }
    *(float4*)&f[(size_t)n * DD + d8]     = make_float4(fs[0], fs[1], fs[2], fs[3]);
    *(float4*)&f[(size_t)n * DD + d8 + 4] = make_float4(fs[4], fs[5], fs[6], fs[7]);

    uint32_t hh[4], ll[4];
#pragma unroll
    for (int q = 0; q < 4; q++) {
        __nv_bfloat162 h, l;
        h.x = __float2bfloat16(hs[q*2+0]);
        h.y = __float2bfloat16(hs[q*2+1]);
        l.x = __float2bfloat16(hs[q*2+0] - __bfloat162float(h.x));
        l.y = __float2bfloat16(hs[q*2+1] - __bfloat162float(h.y));
        hh[q] = *(uint32_t*)&h; ll[q] = *(uint32_t*)&l;
    }
    size_t tile = (size_t)(n >> 7) * 8 + (d8 >> 5);
    unsigned off = SW64((unsigned)((n & 127) * 64 + (d8 & 31) * 2));
    *(uint4*)(g_Ahshi + tile * TILE32 + off) = make_uint4(hh[0], hh[1], hh[2], hh[3]);
    *(uint4*)(g_Ahslo + tile * TILE32 + off) = make_uint4(ll[0], ll[1], ll[2], ll[3]);
}

// ---------------- launch -----------------------------------------------------
extern "C" void kernel_launch(void* const* d_in, const int* in_sizes, int n_in,
                              void* d_out, int out_size)
{
    const float* tensor  = (const float*)d_in[0];
    const int*   indices = (const int*)  d_in[1];
    const float* W_w     = (const float*)d_in[2];
    const float* W_b     = (const float*)d_in[3];
    const float* U_f     = (const float*)d_in[4];
    const float* U_iuo   = (const float*)d_in[5];

    float* out_h = (float*)d_out;
    float* out_c = out_h + (size_t)LL * NN * DD;

    float* wfb;  cudaGetSymbolAddress((void**)&wfb,  g_Wf);
    float* hu;   cudaGetSymbolAddress((void**)&hu,   g_Hu);
    float* fbuf; cudaGetSymbolAddress((void**)&fbuf, g_f);
    unsigned char *axhi, *axlo, *ahshi, *ahslo, *ahhi, *ahlo;
    cudaGetSymbolAddress((void**)&axhi,  g_Axhi);
    cudaGetSymbolAddress((void**)&axlo,  g_Axlo);
    cudaGetSymbolAddress((void**)&ahshi, g_Ahshi);
    cudaGetSymbolAddress((void**)&ahslo, g_Ahslo);
    cudaGetSymbolAddress((void**)&ahhi,  g_Ahhi);
    cudaGetSymbolAddress((void**)&ahlo,  g_Ahlo);

    const int SMEM_DYN  = 3 * (int)STG;    // 96KB for gemm_mma
    const int SMEM_FUSE = 3 * (int)STGF;   // 72KB for fused kernel
    cudaFuncSetAttribute(gemm_mma, cudaFuncAttributeMaxDynamicSharedMemorySize, SMEM_DYN);
    cudaFuncSetAttribute(gemm_iuo_gates, cudaFuncAttributeMaxDynamicSharedMemorySize, SMEM_FUSE);

    const dim3 blk(256);
    const size_t LVL_TILES = (size_t)(NN / 128) * 8 * TILE32;

    // one-time prep
    prep_small<<<(256 * 256) / 256, blk>>>(W_w, U_f);
    prep_ext<<<(512 * 768 + 255) / 256, blk>>>(W_w, U_iuo);
    xconv_kernel<<<(NTOT * 64) / 256, blk>>>(tensor);

    // batched Wf = x @ W_f + b_f for levels 1..7
    gemm_mma<<<dim3(2, 7 * NN / 128), blk, SMEM_DYN>>>(
        axhi + LVL_TILES, axlo + LVL_TILES, axhi, axlo, 8, 0,
        W_b, wfb + (size_t)NN * DD, DD);

    for (int l = 0; l < LL; l++) {
        const int*   idx = indices + (size_t)l * NN * KC;
        const float* hp  = (l == 0) ? nullptr : out_h + (size_t)(l - 1) * NN * DD;
        const float* cp  = (l == 0) ? nullptr : out_c + (size_t)(l - 1) * NN * DD;

        // Hu = h_prev @ U_f
        if (l > 0)
            gemm_mma<<<dim3(2, NN / 128), blk, SMEM_DYN>>>(
                ahhi, ahlo, ahhi, ahlo, 8, 16, nullptr, hu, DD);

        // gather: hsum tiles + f
        gather_kernel<<<NN / 8, blk>>>(idx, hp, cp, hu,
                                       wfb + (size_t)l * NN * DD, fbuf);

        // fused iuo GEMM + gates: writes out_h/out_c + h tiles
        gemm_iuo_gates<<<dim3(2, NN / 64), blk, SMEM_FUSE>>>(
            ahshi, ahslo,
            axhi + (size_t)l * LVL_TILES,
            axlo + (size_t)l * LVL_TILES,
            W_b + 256, fbuf,
            out_h + (size_t)l * NN * DD,
            out_c + (size_t)l * NN * DD);
    }
}

// round 11
// speedup vs baseline: 1.0959x; 1.0959x over previous
#include <cuda_runtime.h>
#include <cuda_bf16.h>
#include <cstdint>
#include <math.h>

#define LL   8
#define NN   16384
#define KC   16
#define DD   256
#define D4   (4*DD)
#define D3   (3*DD)
#define NTOT (LL*NN)            // 131072

#define SW64(o) ((o) ^ (((o) >> 3) & 0x30))
#define TILE32 8192             // one 128x32 bf16 tile (64B rows, SW64)
#define STG 32768u              // stage: Ahi|Alo|Bhi|Blo x 8KB

__device__ __forceinline__ uint32_t smem_u32(const void* p) {
    uint32_t a;
    asm("{ .reg .u64 t; cvta.to.shared.u64 t, %1; cvt.u32.u64 %0, t; }" : "=r"(a) : "l"(p));
    return a;
}
__device__ __forceinline__ void ldsm_x4(uint32_t& r0, uint32_t& r1, uint32_t& r2,
                                        uint32_t& r3, uint32_t addr) {
    asm volatile("ldmatrix.sync.aligned.m8n8.x4.shared.b16 {%0,%1,%2,%3}, [%4];"
                 : "=r"(r0), "=r"(r1), "=r"(r2), "=r"(r3) : "r"(addr));
}
__device__ __forceinline__ void mma16816(float* c, const uint32_t* a, const uint32_t* b) {
    asm volatile("mma.sync.aligned.m16n8k16.row.col.f32.bf16.bf16.f32 "
                 "{%0,%1,%2,%3}, {%4,%5,%6,%7}, {%8,%9}, {%0,%1,%2,%3};"
                 : "+f"(c[0]), "+f"(c[1]), "+f"(c[2]), "+f"(c[3])
                 : "r"(a[0]), "r"(a[1]), "r"(a[2]), "r"(a[3]), "r"(b[0]), "r"(b[1]));
}
__device__ __forceinline__ float sigmoid_fast(float z) {
    float t;
    asm("tanh.approx.f32 %0, %1;" : "=f"(t) : "f"(0.5f * z));
    return fmaf(0.5f, t, 0.5f);
}
// HW-exp based, ~2e-6 rel err (safe: non-compounding magnitude)
__device__ __forceinline__ float sigmoid_hw(float z) {
    return 1.f / (1.f + __expf(-z));
}
__device__ __forceinline__ float tanh_hw(float z) {
    // 1 - 2/(e^{2z}+1): stable at +/-inf, ~2e-6 rel err
    return 1.f - 2.f / (__expf(2.f * z) + 1.f);
}
#define CP_ASYNC16(dst, src) \
    asm volatile("cp.async.cg.shared.global [%0], [%1], 16;" :: "r"(dst), "l"(src))
#define CP_COMMIT asm volatile("cp.async.commit_group;" ::: "memory")
#define CP_WAIT1  asm volatile("cp.async.wait_group 1;" ::: "memory")
#define CP_WAIT0  asm volatile("cp.async.wait_group 0;" ::: "memory")

// ---------------- scratch (device globals) ---------------------------------
__device__ float g_Wf  [NTOT * DD];
__device__ float g_Hu  [NN * DD];
__device__ float g_f   [NN * DD];
__device__ float g_iuo [NN * D3];
// A operands: 128x32 bf16 tiles, 8 per 128-row block (K=256)
__device__ __align__(1024) unsigned char g_Axhi[NTOT/128 * 8 * TILE32];
__device__ __align__(1024) unsigned char g_Axlo[NTOT/128 * 8 * TILE32];
__device__ __align__(1024) unsigned char g_Ahshi[NN/128 * 8 * TILE32];
__device__ __align__(1024) unsigned char g_Ahslo[NN/128 * 8 * TILE32];
__device__ __align__(1024) unsigned char g_Ahhi [NN/128 * 8 * TILE32];
__device__ __align__(1024) unsigned char g_Ahlo [NN/128 * 8 * TILE32];
// B tiles: Wf: 0..15 (2nb x 8kc) | U_f: 16..31 | B_ext: 32..127 (6nb x 16kc)
__device__ __align__(1024) unsigned char g_Bhi[128 * TILE32];
__device__ __align__(1024) unsigned char g_Blo[128 * TILE32];

// ---------------- weight prep ----------------------------------------------
__device__ __forceinline__ void put_b(unsigned tile, int n_loc, int k_loc, float v) {
    __nv_bfloat16 hi = __float2bfloat16(v);
    __nv_bfloat16 lo = __float2bfloat16(v - __bfloat162float(hi));
    unsigned off = tile * TILE32 + SW64((unsigned)(n_loc * 64 + k_loc * 2));
    *(__nv_bfloat16*)(g_Bhi + off) = hi;
    *(__nv_bfloat16*)(g_Blo + off) = lo;
}
__global__ __launch_bounds__(256)
void prep_small(const float* __restrict__ W_w, const float* __restrict__ U_f)
{
    int idx = blockIdx.x * blockDim.x + threadIdx.x;
    int n = idx & 255, k = idx >> 8;
    put_b( 0 + (n >> 7) * 8 + (k >> 5), n & 127, k & 31, W_w[k * 1024 + n]);
    put_b(16 + (n >> 7) * 8 + (k >> 5), n & 127, k & 31, U_f[k * 256 + n]);
}
__global__ __launch_bounds__(256)
void prep_ext(const float* __restrict__ W_w, const float* __restrict__ U_iuo)
{
    int idx = blockIdx.x * blockDim.x + threadIdx.x;
    if (idx >= 512 * 768) return;
    int n = idx % 768, k = idx / 768;
    float v = (k < 256) ? U_iuo[k * 768 + n] : W_w[(k - 256) * 1024 + 256 + n];
    put_b(32 + (n >> 7) * 16 + (k >> 5), n & 127, k & 31, v);
}

// ---------------- x -> bf16 hi/lo tiles -------------------------------------
__global__ __launch_bounds__(256)
void xconv_kernel(const float* __restrict__ x)
{
    int t = blockIdx.x * blockDim.x + threadIdx.x;
    int n = t >> 6, c4 = t & 63;
    float4 v = *(const float4*)&x[(size_t)t * 4];
    __nv_bfloat162 h0, h1, l0, l1;
    h0.x = __float2bfloat16(v.x); h0.y = __float2bfloat16(v.y);
    h1.x = __float2bfloat16(v.z); h1.y = __float2bfloat16(v.w);
    l0.x = __float2bfloat16(v.x - __bfloat162float(h0.x));
    l0.y = __float2bfloat16(v.y - __bfloat162float(h0.y));
    l1.x = __float2bfloat16(v.z - __bfloat162float(h1.x));
    l1.y = __float2bfloat16(v.w - __bfloat162float(h1.y));
    size_t tile = (size_t)(n >> 7) * 8 + (c4 >> 3);
    unsigned off = SW64((unsigned)((n & 127) * 64 + (c4 & 7) * 8));
    uint2 hh, ll;
    hh.x = *(uint32_t*)&h0; hh.y = *(uint32_t*)&h1;
    ll.x = *(uint32_t*)&l0; ll.y = *(uint32_t*)&l1;
    *(uint2*)(g_Axhi + tile * TILE32 + off) = hh;
    *(uint2*)(g_Axlo + tile * TILE32 + off) = ll;
}

// ---------------- 256-thread HMMA GEMM, 128x128 tile, 3-stage, 1 sync/kc ---
__global__ __launch_bounds__(256, 2)
void gemm_mma(const unsigned char* __restrict__ A0h, const unsigned char* __restrict__ A0l,
              const unsigned char* __restrict__ A1h, const unsigned char* __restrict__ A1l,
              int kchunks, int btile_base,
              const float* __restrict__ bias, float* __restrict__ C, int Nc)
{
    extern __shared__ char smem[];   // 3 stages x [Ahi|Alo|Bhi|Blo] x 8KB
    const uint32_t sb = smem_u32(smem);
    const int tid = threadIdx.x, wid = tid >> 5, lane = tid & 31;
    const int wm = wid & 3, wn = wid >> 2;
    const int mb = blockIdx.y, bn = blockIdx.x * 128;

    float acc[2][8][4];
#pragma unroll
    for (int i = 0; i < 2; i++)
#pragma unroll
        for (int j = 0; j < 8; j++)
#pragma unroll
            for (int q = 0; q < 4; q++) acc[i][j][q] = 0.f;

    const int a_row16 = (lane & 7) + ((lane >> 3) & 1) * 8;
    const int a_kb    = (lane >> 4) * 16;
    const int b_row16 = (lane & 7) + ((lane >> 4) << 3);
    const int b_kb    = ((lane >> 3) & 1) * 16;

    uint32_t aRow[2], aXor[2], bRow[4], bXor[4];
#pragma unroll
    for (int mt = 0; mt < 2; mt++) {
        uint32_t r = (uint32_t)(wm * 32 + mt * 16 + a_row16);
        aRow[mt] = r * 64u; aXor[mt] = (r & 6) * 8u;
    }
#pragma unroll
    for (int np = 0; np < 4; np++) {
        uint32_t r = (uint32_t)(wn * 64 + np * 16 + b_row16);
        bRow[np] = 16384u + r * 64u; bXor[np] = (r & 6) * 8u;
    }

    auto load_stage = [&](int stg, int kc) {
        const unsigned char *ah, *al;
        int kcl;
        if (kc < 8) { ah = A0h; al = A0l; kcl = kc; }
        else        { ah = A1h; al = A1l; kcl = kc - 8; }
        size_t at = ((size_t)mb * 8 + kcl) * TILE32;
        size_t bt = (size_t)(btile_base + blockIdx.x * kchunks + kc) * TILE32;
        const unsigned char* srcs[4] = { ah + at, al + at, g_Bhi + bt, g_Blo + bt };
        uint32_t base = sb + (uint32_t)stg * STG;
#pragma unroll
        for (int j = 0; j < 4; j++) {
            uint32_t d = base + j * TILE32 + tid * 16;
            const unsigned char* s = srcs[j] + tid * 16;
            CP_ASYNC16(d, s);
            CP_ASYNC16(d + 4096, s + 4096);
        }
        CP_COMMIT;
    };

    load_stage(0, 0);
    load_stage(1, 1);

    int cons = 0, pf = 2;
    for (int kc = 0; kc < kchunks; kc++) {
        if (kc + 1 < kchunks) CP_WAIT1; else CP_WAIT0;
        __syncthreads();    // chunk kc visible to all; slot 'pf' free for reuse
        if (kc + 2 < kchunks) {
            load_stage(pf, kc + 2);
            pf = (pf == 2) ? 0 : pf + 1;
        }
        const uint32_t stg = sb + (uint32_t)cons * STG;
        cons = (cons == 2) ? 0 : cons + 1;

#pragma unroll
        for (int ks = 0; ks < 2; ks++) {
            const uint32_t ka = (uint32_t)(ks * 32 + a_kb);
            const uint32_t kb = (uint32_t)(ks * 32 + b_kb);
            uint32_t av[2][4], bv[4][4];
            // pass 1: A-hi x B-hi
#pragma unroll
            for (int mt = 0; mt < 2; mt++)
                ldsm_x4(av[mt][0], av[mt][1], av[mt][2], av[mt][3],
                        stg + aRow[mt] + (ka ^ aXor[mt]));
#pragma unroll
            for (int np = 0; np < 4; np++)
                ldsm_x4(bv[np][0], bv[np][1], bv[np][2], bv[np][3],
                        stg + bRow[np] + (kb ^ bXor[np]));
#pragma unroll
            for (int mt = 0; mt < 2; mt++)
#pragma unroll
                for (int nt = 0; nt < 8; nt++)
                    mma16816(acc[mt][nt], av[mt], &bv[nt >> 1][(nt & 1) * 2]);
            // pass 2: A-lo x B-hi (reuse B fragments)
#pragma unroll
            for (int mt = 0; mt < 2; mt++)
                ldsm_x4(av[mt][0], av[mt][1], av[mt][2], av[mt][3],
                        stg + TILE32 + aRow[mt] + (ka ^ aXor[mt]));
#pragma unroll
            for (int mt = 0; mt < 2; mt++)
#pragma unroll
                for (int nt = 0; nt < 8; nt++)
                    mma16816(acc[mt][nt], av[mt], &bv[nt >> 1][(nt & 1) * 2]);
            // pass 3: A-hi x B-lo
#pragma unroll
            for (int mt = 0; mt < 2; mt++)
                ldsm_x4(av[mt][0], av[mt][1], av[mt][2], av[mt][3],
                        stg + aRow[mt] + (ka ^ aXor[mt]));
#pragma unroll
            for (int np = 0; np < 4; np++)
                ldsm_x4(bv[np][0], bv[np][1], bv[np][2], bv[np][3],
                        stg + TILE32 + bRow[np] + (kb ^ bXor[np]));
#pragma unroll
            for (int mt = 0; mt < 2; mt++)
#pragma unroll
                for (int nt = 0; nt < 8; nt++)
                    mma16816(acc[mt][nt], av[mt], &bv[nt >> 1][(nt & 1) * 2]);
        }
    }

    // epilogue
    const int r0 = lane >> 2, c0 = (lane & 3) * 2;
    const int bm = mb * 128;
#pragma unroll
    for (int mt = 0; mt < 2; mt++) {
#pragma unroll
        for (int nt = 0; nt < 8; nt++) {
            int row = bm + wm * 32 + mt * 16 + r0;
            int col = bn + wn * 64 + nt * 8 + c0;
            float b0 = 0.f, b1 = 0.f;
            if (bias) { b0 = bias[col]; b1 = bias[col + 1]; }
            float2 v0, v1;
            v0.x = acc[mt][nt][0] + b0; v0.y = acc[mt][nt][1] + b1;
            v1.x = acc[mt][nt][2] + b0; v1.y = acc[mt][nt][3] + b1;
            *(float2*)&C[(size_t)row * Nc + col]       = v0;
            *(float2*)&C[(size_t)(row + 8) * Nc + col] = v1;
        }
    }
}

// ---------------- gather: 8 nodes/block, 8 dims/thread, f32 tables ---------
__global__ __launch_bounds__(256)
void gather_kernel(const int* __restrict__ idx,
                   const float* __restrict__ h_prev,
                   const float* __restrict__ c_prev,
                   const float* __restrict__ Hu,
                   const float* __restrict__ Wf,
                   float* __restrict__ f)
{
    const int nb = blockIdx.x * 8;
    const int t  = threadIdx.x;
    const int ln = t >> 5;
    const int n  = nb + ln;
    const int d8 = (t & 31) * 8;

    __shared__ int sidx[8][KC];
    if (t < 128) sidx[t >> 4][t & 15] = idx[(nb + (t >> 4)) * KC + (t & 15)];
    __syncthreads();

    float hs[8] = {0,0,0,0,0,0,0,0};
    float fs[8] = {0,0,0,0,0,0,0,0};
    if (h_prev) {
        float4 wf0 = *(const float4*)&Wf[(size_t)n * DD + d8];
        float4 wf1 = *(const float4*)&Wf[(size_t)n * DD + d8 + 4];
        const float wf[8] = {wf0.x, wf0.y, wf0.z, wf0.w, wf1.x, wf1.y, wf1.z, wf1.w};
#pragma unroll
        for (int k = 0; k < KC; k++) {
            int j = sidx[ln][k];
            if (j >= 1) {
                size_t r = (size_t)(j - 1) * DD + d8;
                float4 h0 = *(const float4*)&h_prev[r];
                float4 h1 = *(const float4*)&h_prev[r + 4];
                float4 u0 = *(const float4*)&Hu[r];
                float4 u1 = *(const float4*)&Hu[r + 4];
                float4 c0 = *(const float4*)&c_prev[r];
                float4 c1 = *(const float4*)&c_prev[r + 4];
                const float hv[8] = {h0.x, h0.y, h0.z, h0.w, h1.x, h1.y, h1.z, h1.w};
                const float uv[8] = {u0.x, u0.y, u0.z, u0.w, u1.x, u1.y, u1.z, u1.w};
                const float cv[8] = {c0.x, c0.y, c0.z, c0.w, c1.x, c1.y, c1.z, c1.w};
#pragma unroll
                for (int q = 0; q < 8; q++) {
                    hs[q] += hv[q];
                    fs[q] += sigmoid_fast(wf[q] + uv[q]) * cv[q];
                }
            }
        }
    }
    *(float4*)&f[(size_t)n * DD + d8]     = make_float4(fs[0], fs[1], fs[2], fs[3]);
    *(float4*)&f[(size_t)n * DD + d8 + 4] = make_float4(fs[4], fs[5], fs[6], fs[7]);

    uint32_t hh[4], ll[4];
#pragma unroll
    for (int q = 0; q < 4; q++) {
        __nv_bfloat162 h, l;
        h.x = __float2bfloat16(hs[q*2+0]);
        h.y = __float2bfloat16(hs[q*2+1]);
        l.x = __float2bfloat16(hs[q*2+0] - __bfloat162float(h.x));
        l.y = __float2bfloat16(hs[q*2+1] - __bfloat162float(h.y));
        hh[q] = *(uint32_t*)&h; ll[q] = *(uint32_t*)&l;
    }
    size_t tile = (size_t)(n >> 7) * 8 + (d8 >> 5);
    unsigned off = SW64((unsigned)((n & 127) * 64 + (d8 & 31) * 2));
    *(uint4*)(g_Ahshi + tile * TILE32 + off) = make_uint4(hh[0], hh[1], hh[2], hh[3]);
    *(uint4*)(g_Ahslo + tile * TILE32 + off) = make_uint4(ll[0], ll[1], ll[2], ll[3]);
}

// ---------------- gates: 4 dims/thread, HW-exp transcendentals --------------
__global__ __launch_bounds__(256)
void gates_kernel(const float* __restrict__ iuo, const float* __restrict__ f,
                  float* __restrict__ out_h, float* __restrict__ out_c)
{
    const int t  = blockIdx.x * blockDim.x + threadIdx.x;
    const int n  = t >> 6;
    const int d4 = (t & 63) * 4;

    const float* iu = &iuo[(size_t)n * D3];
    float4 vi = *(const float4*)&iu[d4];
    float4 vu = *(const float4*)&iu[DD + d4];
    float4 vo = *(const float4*)&iu[2 * DD + d4];
    float4 ff = *(const float4*)&f[(size_t)n * DD + d4];

    float cc[4], hh[4];
    const float iv[4] = {vi.x, vi.y, vi.z, vi.w};
    const float uv[4] = {vu.x, vu.y, vu.z, vu.w};
    const float ov[4] = {vo.x, vo.y, vo.z, vo.w};
    const float fv[4] = {ff.x, ff.y, ff.z, ff.w};
#pragma unroll
    for (int q = 0; q < 4; q++) {
        cc[q] = sigmoid_hw(iv[q]) * tanh_hw(uv[q]) + fv[q];
        hh[q] = sigmoid_hw(ov[q]) * tanh_hw(cc[q]);
    }
    *(float4*)&out_c[(size_t)n * DD + d4] = make_float4(cc[0], cc[1], cc[2], cc[3]);
    *(float4*)&out_h[(size_t)n * DD + d4] = make_float4(hh[0], hh[1], hh[2], hh[3]);

    // h -> bf16 hi/lo tiles (4 dims = uint2 per buffer)
    __nv_bfloat162 hb0, hb1, lb0, lb1;
    hb0.x = __float2bfloat16(hh[0]); hb0.y = __float2bfloat16(hh[1]);
    hb1.x = __float2bfloat16(hh[2]); hb1.y = __float2bfloat16(hh[3]);
    lb0.x = __float2bfloat16(hh[0] - __bfloat162float(hb0.x));
    lb0.y = __float2bfloat16(hh[1] - __bfloat162float(hb0.y));
    lb1.x = __float2bfloat16(hh[2] - __bfloat162float(hb1.x));
    lb1.y = __float2bfloat16(hh[3] - __bfloat162float(hb1.y));
    size_t tile = (size_t)(n >> 7) * 8 + (d4 >> 5);
    unsigned off = SW64((unsigned)((n & 127) * 64 + (d4 & 31) * 2));
    uint2 hv2, lv2;
    hv2.x = *(uint32_t*)&hb0; hv2.y = *(uint32_t*)&hb1;
    lv2.x = *(uint32_t*)&lb0; lv2.y = *(uint32_t*)&lb1;
    *(uint2*)(g_Ahhi + tile * TILE32 + off) = hv2;
    *(uint2*)(g_Ahlo + tile * TILE32 + off) = lv2;
}

// ---------------- launch -----------------------------------------------------
extern "C" void kernel_launch(void* const* d_in, const int* in_sizes, int n_in,
                              void* d_out, int out_size)
{
    const float* tensor  = (const float*)d_in[0];
    const int*   indices = (const int*)  d_in[1];
    const float* W_w     = (const float*)d_in[2];
    const float* W_b     = (const float*)d_in[3];
    const float* U_f     = (const float*)d_in[4];
    const float* U_iuo   = (const float*)d_in[5];

    float* out_h = (float*)d_out;
    float* out_c = out_h + (size_t)LL * NN * DD;

    float* wfb;  cudaGetSymbolAddress((void**)&wfb,  g_Wf);
    float* hu;   cudaGetSymbolAddress((void**)&hu,   g_Hu);
    float* fbuf; cudaGetSymbolAddress((void**)&fbuf, g_f);
    float* iuo;  cudaGetSymbolAddress((void**)&iuo,  g_iuo);
    unsigned char *axhi, *axlo, *ahshi, *ahslo, *ahhi, *ahlo;
    cudaGetSymbolAddress((void**)&axhi,  g_Axhi);
    cudaGetSymbolAddress((void**)&axlo,  g_Axlo);
    cudaGetSymbolAddress((void**)&ahshi, g_Ahshi);
    cudaGetSymbolAddress((void**)&ahslo, g_Ahslo);
    cudaGetSymbolAddress((void**)&ahhi,  g_Ahhi);
    cudaGetSymbolAddress((void**)&ahlo,  g_Ahlo);

    const int SMEM_DYN = 3 * (int)STG;   // 96KB -> 2 CTAs/SM
    cudaFuncSetAttribute(gemm_mma, cudaFuncAttributeMaxDynamicSharedMemorySize, SMEM_DYN);

    const dim3 blk(256);
    const size_t LVL_TILES = (size_t)(NN / 128) * 8 * TILE32;

    // one-time prep
    prep_small<<<(256 * 256) / 256, blk>>>(W_w, U_f);
    prep_ext<<<(512 * 768 + 255) / 256, blk>>>(W_w, U_iuo);
    xconv_kernel<<<(NTOT * 64) / 256, blk>>>(tensor);

    // batched Wf = x @ W_f + b_f for levels 1..7
    gemm_mma<<<dim3(2, 7 * NN / 128), blk, SMEM_DYN>>>(
        axhi + LVL_TILES, axlo + LVL_TILES, axhi, axlo, 8, 0,
        W_b, wfb + (size_t)NN * DD, DD);

    for (int l = 0; l < LL; l++) {
        const int*   idx = indices + (size_t)l * NN * KC;
        const float* hp  = (l == 0) ? nullptr : out_h + (size_t)(l - 1) * NN * DD;
        const float* cp  = (l == 0) ? nullptr : out_c + (size_t)(l - 1) * NN * DD;

        if (l > 0)
            gemm_mma<<<dim3(2, NN / 128), blk, SMEM_DYN>>>(
                ahhi, ahlo, ahhi, ahlo, 8, 16, nullptr, hu, DD);

        gather_kernel<<<NN / 8, blk>>>(idx, hp, cp, hu,
                                       wfb + (size_t)l * NN * DD, fbuf);

        gemm_mma<<<dim3(6, NN / 128), blk, SMEM_DYN>>>(
            ahshi, ahslo,
            axhi + (size_t)l * LVL_TILES,
            axlo + (size_t)l * LVL_TILES,
            16, 32, W_b + 256, iuo, D3);

        gates_kernel<<<(NN * DD / 4) / 256, blk>>>(iuo, fbuf,
                                                   out_h + (size_t)l * NN * DD,
                                                   out_c + (size_t)l * NN * DD);
    }
}

// round 12
// speedup vs baseline: 1.1310x; 1.0321x over previous
#include <cuda_runtime.h>
#include <cuda_bf16.h>
#include <cstdint>
#include <math.h>

#define LL   8
#define NN   16384
#define KC   16
#define DD   256
#define D4   (4*DD)
#define D3   (3*DD)
#define NTOT (LL*NN)            // 131072

#define SW64(o) ((o) ^ (((o) >> 3) & 0x30))
#define TILE32 8192             // one 128x32 bf16 tile (64B rows, SW64)
#define STG 32768u              // stage: Ahi|Alo|Bhi|Blo x 8KB

__device__ __forceinline__ uint32_t smem_u32(const void* p) {
    uint32_t a;
    asm("{ .reg .u64 t; cvta.to.shared.u64 t, %1; cvt.u32.u64 %0, t; }" : "=r"(a) : "l"(p));
    return a;
}
__device__ __forceinline__ void ldsm_x4(uint32_t& r0, uint32_t& r1, uint32_t& r2,
                                        uint32_t& r3, uint32_t addr) {
    asm volatile("ldmatrix.sync.aligned.m8n8.x4.shared.b16 {%0,%1,%2,%3}, [%4];"
                 : "=r"(r0), "=r"(r1), "=r"(r2), "=r"(r3) : "r"(addr));
}
__device__ __forceinline__ void mma16816(float* c, const uint32_t* a, const uint32_t* b) {
    asm volatile("mma.sync.aligned.m16n8k16.row.col.f32.bf16.bf16.f32 "
                 "{%0,%1,%2,%3}, {%4,%5,%6,%7}, {%8,%9}, {%0,%1,%2,%3};"
                 : "+f"(c[0]), "+f"(c[1]), "+f"(c[2]), "+f"(c[3])
                 : "r"(a[0]), "r"(a[1]), "r"(a[2]), "r"(a[3]), "r"(b[0]), "r"(b[1]));
}
__device__ __forceinline__ float sigmoid_fast(float z) {
    float t;
    asm("tanh.approx.f32 %0, %1;" : "=f"(t) : "f"(0.5f * z));
    return fmaf(0.5f, t, 0.5f);
}
// HW-exp based, ~2e-6 rel err (safe: non-compounding magnitude)
__device__ __forceinline__ float sigmoid_hw(float z) {
    return 1.f / (1.f + __expf(-z));
}
__device__ __forceinline__ float tanh_hw(float z) {
    return 1.f - 2.f / (__expf(2.f * z) + 1.f);
}
#define CP_ASYNC16(dst, src) \
    asm volatile("cp.async.cg.shared.global [%0], [%1], 16;" :: "r"(dst), "l"(src))
#define CP_COMMIT asm volatile("cp.async.commit_group;" ::: "memory")
#define CP_WAIT2  asm volatile("cp.async.wait_group 2;" ::: "memory")
#define CP_WAIT1  asm volatile("cp.async.wait_group 1;" ::: "memory")
#define CP_WAIT0  asm volatile("cp.async.wait_group 0;" ::: "memory")

// ---------------- scratch (device globals) ---------------------------------
__device__ float g_Wf  [NTOT * DD];
__device__ float g_Hu  [NN * DD];
__device__ float g_f   [NN * DD];
__device__ float g_iuo [NN * D3];
// A operands: 128x32 bf16 tiles, 8 per 128-row block (K=256)
__device__ __align__(1024) unsigned char g_Axhi[NTOT/128 * 8 * TILE32];
__device__ __align__(1024) unsigned char g_Axlo[NTOT/128 * 8 * TILE32];
__device__ __align__(1024) unsigned char g_Ahshi[NN/128 * 8 * TILE32];
__device__ __align__(1024) unsigned char g_Ahslo[NN/128 * 8 * TILE32];
__device__ __align__(1024) unsigned char g_Ahhi [NN/128 * 8 * TILE32];
__device__ __align__(1024) unsigned char g_Ahlo [NN/128 * 8 * TILE32];
// B tiles: Wf: 0..15 (2nb x 8kc) | U_f: 16..31 | B_ext: 32..127 (6nb x 16kc)
__device__ __align__(1024) unsigned char g_Bhi[128 * TILE32];
__device__ __align__(1024) unsigned char g_Blo[128 * TILE32];

// ---------------- weight prep ----------------------------------------------
__device__ __forceinline__ void put_b(unsigned tile, int n_loc, int k_loc, float v) {
    __nv_bfloat16 hi = __float2bfloat16(v);
    __nv_bfloat16 lo = __float2bfloat16(v - __bfloat162float(hi));
    unsigned off = tile * TILE32 + SW64((unsigned)(n_loc * 64 + k_loc * 2));
    *(__nv_bfloat16*)(g_Bhi + off) = hi;
    *(__nv_bfloat16*)(g_Blo + off) = lo;
}
__global__ __launch_bounds__(256)
void prep_small(const float* __restrict__ W_w, const float* __restrict__ U_f)
{
    int idx = blockIdx.x * blockDim.x + threadIdx.x;
    int n = idx & 255, k = idx >> 8;
    put_b( 0 + (n >> 7) * 8 + (k >> 5), n & 127, k & 31, W_w[k * 1024 + n]);
    put_b(16 + (n >> 7) * 8 + (k >> 5), n & 127, k & 31, U_f[k * 256 + n]);
}
__global__ __launch_bounds__(256)
void prep_ext(const float* __restrict__ W_w, const float* __restrict__ U_iuo)
{
    int idx = blockIdx.x * blockDim.x + threadIdx.x;
    if (idx >= 512 * 768) return;
    int n = idx % 768, k = idx / 768;
    float v = (k < 256) ? U_iuo[k * 768 + n] : W_w[(k - 256) * 1024 + 256 + n];
    put_b(32 + (n >> 7) * 16 + (k >> 5), n & 127, k & 31, v);
}

// ---------------- x -> bf16 hi/lo tiles -------------------------------------
__global__ __launch_bounds__(256)
void xconv_kernel(const float* __restrict__ x)
{
    int t = blockIdx.x * blockDim.x + threadIdx.x;
    int n = t >> 6, c4 = t & 63;
    float4 v = *(const float4*)&x[(size_t)t * 4];
    __nv_bfloat162 h0, h1, l0, l1;
    h0.x = __float2bfloat16(v.x); h0.y = __float2bfloat16(v.y);
    h1.x = __float2bfloat16(v.z); h1.y = __float2bfloat16(v.w);
    l0.x = __float2bfloat16(v.x - __bfloat162float(h0.x));
    l0.y = __float2bfloat16(v.y - __bfloat162float(h0.y));
    l1.x = __float2bfloat16(v.z - __bfloat162float(h1.x));
    l1.y = __float2bfloat16(v.w - __bfloat162float(h1.y));
    size_t tile = (size_t)(n >> 7) * 8 + (c4 >> 3);
    unsigned off = SW64((unsigned)((n & 127) * 64 + (c4 & 7) * 8));
    uint2 hh, ll;
    hh.x = *(uint32_t*)&h0; hh.y = *(uint32_t*)&h1;
    ll.x = *(uint32_t*)&l0; ll.y = *(uint32_t*)&l1;
    *(uint2*)(g_Axhi + tile * TILE32 + off) = hh;
    *(uint2*)(g_Axlo + tile * TILE32 + off) = ll;
}

// ---------------- 256-thread HMMA GEMM, 128x128 tile, 3-stage (round-9) ----
__global__ __launch_bounds__(256, 2)
void gemm_mma(const unsigned char* __restrict__ A0h, const unsigned char* __restrict__ A0l,
              const unsigned char* __restrict__ A1h, const unsigned char* __restrict__ A1l,
              int kchunks, int btile_base,
              const float* __restrict__ bias, float* __restrict__ C, int Nc)
{
    extern __shared__ char smem[];   // 3 stages x [Ahi|Alo|Bhi|Blo] x 8KB
    const uint32_t sb = smem_u32(smem);
    const int tid = threadIdx.x, wid = tid >> 5, lane = tid & 31;
    const int wm = wid & 3, wn = wid >> 2;
    const int mb = blockIdx.y, bn = blockIdx.x * 128;

    float acc[2][8][4];
#pragma unroll
    for (int i = 0; i < 2; i++)
#pragma unroll
        for (int j = 0; j < 8; j++)
#pragma unroll
            for (int q = 0; q < 4; q++) acc[i][j][q] = 0.f;

    const int a_row16 = (lane & 7) + ((lane >> 3) & 1) * 8;
    const int a_kb    = (lane >> 4) * 16;
    const int b_row16 = (lane & 7) + ((lane >> 4) << 3);
    const int b_kb    = ((lane >> 3) & 1) * 16;

    uint32_t aRow[2], aXor[2], bRow[4], bXor[4];
#pragma unroll
    for (int mt = 0; mt < 2; mt++) {
        uint32_t r = (uint32_t)(wm * 32 + mt * 16 + a_row16);
        aRow[mt] = r * 64u; aXor[mt] = (r & 6) * 8u;
    }
#pragma unroll
    for (int np = 0; np < 4; np++) {
        uint32_t r = (uint32_t)(wn * 64 + np * 16 + b_row16);
        bRow[np] = 16384u + r * 64u; bXor[np] = (r & 6) * 8u;
    }

    auto load_stage = [&](int stg, int kc) {
        const unsigned char *ah, *al;
        int kcl;
        if (kc < 8) { ah = A0h; al = A0l; kcl = kc; }
        else        { ah = A1h; al = A1l; kcl = kc - 8; }
        size_t at = ((size_t)mb * 8 + kcl) * TILE32;
        size_t bt = (size_t)(btile_base + blockIdx.x * kchunks + kc) * TILE32;
        const unsigned char* srcs[4] = { ah + at, al + at, g_Bhi + bt, g_Blo + bt };
        uint32_t base = sb + (uint32_t)stg * STG;
#pragma unroll
        for (int j = 0; j < 4; j++) {
            uint32_t d = base + j * TILE32 + tid * 16;
            const unsigned char* s = srcs[j] + tid * 16;
            CP_ASYNC16(d, s);
            CP_ASYNC16(d + 4096, s + 4096);
        }
        CP_COMMIT;
    };

    load_stage(0, 0);
    load_stage(1, 1);
    load_stage(2, 2);

    int stg_i = 0;
    for (int kc = 0; kc < kchunks; kc++) {
        if      (kc + 2 < kchunks) CP_WAIT2;
        else if (kc + 1 < kchunks) CP_WAIT1;
        else                       CP_WAIT0;
        __syncthreads();

        const uint32_t stg = sb + (uint32_t)stg_i * STG;
#pragma unroll
        for (int ks = 0; ks < 2; ks++) {
            const uint32_t ka = (uint32_t)(ks * 32 + a_kb);
            const uint32_t kb = (uint32_t)(ks * 32 + b_kb);
            uint32_t av[2][4], bv[4][4];
            // pass 1: A-hi x B-hi
#pragma unroll
            for (int mt = 0; mt < 2; mt++)
                ldsm_x4(av[mt][0], av[mt][1], av[mt][2], av[mt][3],
                        stg + aRow[mt] + (ka ^ aXor[mt]));
#pragma unroll
            for (int np = 0; np < 4; np++)
                ldsm_x4(bv[np][0], bv[np][1], bv[np][2], bv[np][3],
                        stg + bRow[np] + (kb ^ bXor[np]));
#pragma unroll
            for (int mt = 0; mt < 2; mt++)
#pragma unroll
                for (int nt = 0; nt < 8; nt++)
                    mma16816(acc[mt][nt], av[mt], &bv[nt >> 1][(nt & 1) * 2]);
            // pass 2: A-lo x B-hi (reuse B fragments)
#pragma unroll
            for (int mt = 0; mt < 2; mt++)
                ldsm_x4(av[mt][0], av[mt][1], av[mt][2], av[mt][3],
                        stg + TILE32 + aRow[mt] + (ka ^ aXor[mt]));
#pragma unroll
            for (int mt = 0; mt < 2; mt++)
#pragma unroll
                for (int nt = 0; nt < 8; nt++)
                    mma16816(acc[mt][nt], av[mt], &bv[nt >> 1][(nt & 1) * 2]);
            // pass 3: A-hi x B-lo
#pragma unroll
            for (int mt = 0; mt < 2; mt++)
                ldsm_x4(av[mt][0], av[mt][1], av[mt][2], av[mt][3],
                        stg + aRow[mt] + (ka ^ aXor[mt]));
#pragma unroll
            for (int np = 0; np < 4; np++)
                ldsm_x4(bv[np][0], bv[np][1], bv[np][2], bv[np][3],
                        stg + TILE32 + bRow[np] + (kb ^ bXor[np]));
#pragma unroll
            for (int mt = 0; mt < 2; mt++)
#pragma unroll
                for (int nt = 0; nt < 8; nt++)
                    mma16816(acc[mt][nt], av[mt], &bv[nt >> 1][(nt & 1) * 2]);
        }
        __syncthreads();
        if (kc + 3 < kchunks) load_stage(stg_i, kc + 3);
        stg_i = (stg_i == 2) ? 0 : stg_i + 1;
    }

    // epilogue
    const int r0 = lane >> 2, c0 = (lane & 3) * 2;
    const int bm = mb * 128;
#pragma unroll
    for (int mt = 0; mt < 2; mt++) {
#pragma unroll
        for (int nt = 0; nt < 8; nt++) {
            int row = bm + wm * 32 + mt * 16 + r0;
            int col = bn + wn * 64 + nt * 8 + c0;
            float b0 = 0.f, b1 = 0.f;
            if (bias) { b0 = bias[col]; b1 = bias[col + 1]; }
            float2 v0, v1;
            v0.x = acc[mt][nt][0] + b0; v0.y = acc[mt][nt][1] + b1;
            v1.x = acc[mt][nt][2] + b0; v1.y = acc[mt][nt][3] + b1;
            *(float2*)&C[(size_t)row * Nc + col]       = v0;
            *(float2*)&C[(size_t)(row + 8) * Nc + col] = v1;
        }
    }
}

// ---------------- gather: 8 nodes/block, 8 dims/thread, f32 tables ---------
__global__ __launch_bounds__(256)
void gather_kernel(const int* __restrict__ idx,
                   const float* __restrict__ h_prev,
                   const float* __restrict__ c_prev,
                   const float* __restrict__ Hu,
                   const float* __restrict__ Wf,
                   float* __restrict__ f)
{
    const int nb = blockIdx.x * 8;
    const int t  = threadIdx.x;
    const int ln = t >> 5;
    const int n  = nb + ln;
    const int d8 = (t & 31) * 8;

    __shared__ int sidx[8][KC];
    if (t < 128) sidx[t >> 4][t & 15] = idx[(nb + (t >> 4)) * KC + (t & 15)];
    __syncthreads();

    float hs[8] = {0,0,0,0,0,0,0,0};
    float fs[8] = {0,0,0,0,0,0,0,0};
    if (h_prev) {
        float4 wf0 = *(const float4*)&Wf[(size_t)n * DD + d8];
        float4 wf1 = *(const float4*)&Wf[(size_t)n * DD + d8 + 4];
        const float wf[8] = {wf0.x, wf0.y, wf0.z, wf0.w, wf1.x, wf1.y, wf1.z, wf1.w};
#pragma unroll
        for (int k = 0; k < KC; k++) {
            int j = sidx[ln][k];
            if (j >= 1) {
                size_t r = (size_t)(j - 1) * DD + d8;
                float4 h0 = *(const float4*)&h_prev[r];
                float4 h1 = *(const float4*)&h_prev[r + 4];
                float4 u0 = *(const float4*)&Hu[r];
                float4 u1 = *(const float4*)&Hu[r + 4];
                float4 c0 = *(const float4*)&c_prev[r];
                float4 c1 = *(const float4*)&c_prev[r + 4];
                const float hv[8] = {h0.x, h0.y, h0.z, h0.w, h1.x, h1.y, h1.z, h1.w};
                const float uv[8] = {u0.x, u0.y, u0.z, u0.w, u1.x, u1.y, u1.z, u1.w};
                const float cv[8] = {c0.x, c0.y, c0.z, c0.w, c1.x, c1.y, c1.z, c1.w};
#pragma unroll
                for (int q = 0; q < 8; q++) {
                    hs[q] += hv[q];
                    fs[q] += sigmoid_fast(wf[q] + uv[q]) * cv[q];
                }
            }
        }
    }
    *(float4*)&f[(size_t)n * DD + d8]     = make_float4(fs[0], fs[1], fs[2], fs[3]);
    *(float4*)&f[(size_t)n * DD + d8 + 4] = make_float4(fs[4], fs[5], fs[6], fs[7]);

    uint32_t hh[4], ll[4];
#pragma unroll
    for (int q = 0; q < 4; q++) {
        __nv_bfloat162 h, l;
        h.x = __float2bfloat16(hs[q*2+0]);
        h.y = __float2bfloat16(hs[q*2+1]);
        l.x = __float2bfloat16(hs[q*2+0] - __bfloat162float(h.x));
        l.y = __float2bfloat16(hs[q*2+1] - __bfloat162float(h.y));
        hh[q] = *(uint32_t*)&h; ll[q] = *(uint32_t*)&l;
    }
    size_t tile = (size_t)(n >> 7) * 8 + (d8 >> 5);
    unsigned off = SW64((unsigned)((n & 127) * 64 + (d8 & 31) * 2));
    *(uint4*)(g_Ahshi + tile * TILE32 + off) = make_uint4(hh[0], hh[1], hh[2], hh[3]);
    *(uint4*)(g_Ahslo + tile * TILE32 + off) = make_uint4(ll[0], ll[1], ll[2], ll[3]);
}

// ---------------- gates: 4 dims/thread, HW-exp transcendentals --------------
__global__ __launch_bounds__(256)
void gates_kernel(const float* __restrict__ iuo, const float* __restrict__ f,
                  float* __restrict__ out_h, float* __restrict__ out_c)
{
    const int t  = blockIdx.x * blockDim.x + threadIdx.x;
    const int n  = t >> 6;
    const int d4 = (t & 63) * 4;

    const float* iu = &iuo[(size_t)n * D3];
    float4 vi = *(const float4*)&iu[d4];
    float4 vu = *(const float4*)&iu[DD + d4];
    float4 vo = *(const float4*)&iu[2 * DD + d4];
    float4 ff = *(const float4*)&f[(size_t)n * DD + d4];

    float cc[4], hh[4];
    const float iv[4] = {vi.x, vi.y, vi.z, vi.w};
    const float uv[4] = {vu.x, vu.y, vu.z, vu.w};
    const float ov[4] = {vo.x, vo.y, vo.z, vo.w};
    const float fv[4] = {ff.x, ff.y, ff.z, ff.w};
#pragma unroll
    for (int q = 0; q < 4; q++) {
        cc[q] = sigmoid_hw(iv[q]) * tanh_hw(uv[q]) + fv[q];
        hh[q] = sigmoid_hw(ov[q]) * tanh_hw(cc[q]);
    }
    *(float4*)&out_c[(size_t)n * DD + d4] = make_float4(cc[0], cc[1], cc[2], cc[3]);
    *(float4*)&out_h[(size_t)n * DD + d4] = make_float4(hh[0], hh[1], hh[2], hh[3]);

    __nv_bfloat162 hb0, hb1, lb0, lb1;
    hb0.x = __float2bfloat16(hh[0]); hb0.y = __float2bfloat16(hh[1]);
    hb1.x = __float2bfloat16(hh[2]); hb1.y = __float2bfloat16(hh[3]);
    lb0.x = __float2bfloat16(hh[0] - __bfloat162float(hb0.x));
    lb0.y = __float2bfloat16(hh[1] - __bfloat162float(hb0.y));
    lb1.x = __float2bfloat16(hh[2] - __bfloat162float(hb1.x));
    lb1.y = __float2bfloat16(hh[3] - __bfloat162float(hb1.y));
    size_t tile = (size_t)(n >> 7) * 8 + (d4 >> 5);
    unsigned off = SW64((unsigned)((n & 127) * 64 + (d4 & 31) * 2));
    uint2 hv2, lv2;
    hv2.x = *(uint32_t*)&hb0; hv2.y = *(uint32_t*)&hb1;
    lv2.x = *(uint32_t*)&lb0; lv2.y = *(uint32_t*)&lb1;
    *(uint2*)(g_Ahhi + tile * TILE32 + off) = hv2;
    *(uint2*)(g_Ahlo + tile * TILE32 + off) = lv2;
}

// ---------------- launch -----------------------------------------------------
extern "C" void kernel_launch(void* const* d_in, const int* in_sizes, int n_in,
                              void* d_out, int out_size)
{
    const float* tensor  = (const float*)d_in[0];
    const int*   indices = (const int*)  d_in[1];
    const float* W_w     = (const float*)d_in[2];
    const float* W_b     = (const float*)d_in[3];
    const float* U_f     = (const float*)d_in[4];
    const float* U_iuo   = (const float*)d_in[5];

    float* out_h = (float*)d_out;
    float* out_c = out_h + (size_t)LL * NN * DD;

    float* wfb;  cudaGetSymbolAddress((void**)&wfb,  g_Wf);
    float* hu;   cudaGetSymbolAddress((void**)&hu,   g_Hu);
    float* fbuf; cudaGetSymbolAddress((void**)&fbuf, g_f);
    float* iuo;  cudaGetSymbolAddress((void**)&iuo,  g_iuo);
    unsigned char *axhi, *axlo, *ahshi, *ahslo, *ahhi, *ahlo;
    cudaGetSymbolAddress((void**)&axhi,  g_Axhi);
    cudaGetSymbolAddress((void**)&axlo,  g_Axlo);
    cudaGetSymbolAddress((void**)&ahshi, g_Ahshi);
    cudaGetSymbolAddress((void**)&ahslo, g_Ahslo);
    cudaGetSymbolAddress((void**)&ahhi,  g_Ahhi);
    cudaGetSymbolAddress((void**)&ahlo,  g_Ahlo);

    const int SMEM_DYN = 3 * (int)STG;   // 96KB -> 2 CTAs/SM
    cudaFuncSetAttribute(gemm_mma, cudaFuncAttributeMaxDynamicSharedMemorySize, SMEM_DYN);

    const dim3 blk(256);
    const size_t LVL_TILES = (size_t)(NN / 128) * 8 * TILE32;

    // one-time prep
    prep_small<<<(256 * 256) / 256, blk>>>(W_w, U_f);
    prep_ext<<<(512 * 768 + 255) / 256, blk>>>(W_w, U_iuo);
    xconv_kernel<<<(NTOT * 64) / 256, blk>>>(tensor);

    // batched Wf = x @ W_f + b_f for levels 1..7
    gemm_mma<<<dim3(2, 7 * NN / 128), blk, SMEM_DYN>>>(
        axhi + LVL_TILES, axlo + LVL_TILES, axhi, axlo, 8, 0,
        W_b, wfb + (size_t)NN * DD, DD);

    for (int l = 0; l < LL; l++) {
        const int*   idx = indices + (size_t)l * NN * KC;
        const float* hp  = (l == 0) ? nullptr : out_h + (size_t)(l - 1) * NN * DD;
        const float* cp  = (l == 0) ? nullptr : out_c + (size_t)(l - 1) * NN * DD;

        if (l > 0)
            gemm_mma<<<dim3(2, NN / 128), blk, SMEM_DYN>>>(
                ahhi, ahlo, ahhi, ahlo, 8, 16, nullptr, hu, DD);

        gather_kernel<<<NN / 8, blk>>>(idx, hp, cp, hu,
                                       wfb + (size_t)l * NN * DD, fbuf);

        gemm_mma<<<dim3(6, NN / 128), blk, SMEM_DYN>>>(
            ahshi, ahslo,
            axhi + (size_t)l * LVL_TILES,
            axlo + (size_t)l * LVL_TILES,
            16, 32, W_b + 256, iuo, D3);

        gates_kernel<<<(NN * DD / 4) / 256, blk>>>(iuo, fbuf,
                                                   out_h + (size_t)l * NN * DD,
                                                   out_c + (size_t)l * NN * DD);
    }
}